// round 4
// baseline (speedup 1.0000x reference)
#include <cuda_runtime.h>

#define NN 50000
#define NE 800000
#define C  128
#define NG 128
#define OC 16

// Scratch (static device globals — no allocation in kernel_launch)
__device__ __align__(16) float g_A[NN * C];     // hs = (X@W)*dis  (layer output pre-agg)
__device__ __align__(16) float g_X2[NN * C];    // layer-2 input
__device__ __align__(16) float g_pool[NG * C];
__device__ float g_dis[NN];
__device__ int   g_src[NE];
__device__ int   g_dst[NE];
__device__ int   g_bat[NN];
__device__ int   g_cnt_i[NN];    // in-degree histogram (by dst)
__device__ int   g_cursor[NN];   // fill cursors
__device__ int   g_rs[NN + 1];   // CSR row starts
__device__ int   g_col[NE];      // CSR column (src) ids
__device__ int   g_gcnt[NG];     // nodes per graph
__device__ int   g_is64;

// Detect whether edge_index buffer is int64 or int32.
// int64 little-endian: odd 32-bit words are high halves == 0 (indices < 2^31),
// and even words are valid node ids. int32: odd words are random node ids in
// [0, 50000) — 256 consecutive zeros is impossible for random uniform indices.
__global__ void k_detect(const int* __restrict__ ei_raw) {
    if (threadIdx.x == 0 && blockIdx.x == 0) {
        int hi_or = 0;
        int lo_ok = 1;
        for (int i = 0; i < 256; i++) {
            hi_or |= ei_raw[2 * i + 1];
            int lo = ei_raw[2 * i];
            lo_ok &= (lo >= 0 && lo < NN) ? 1 : 0;
        }
        g_is64 = (hi_or == 0 && lo_ok) ? 1 : 0;
    }
}

__global__ void k_convert(const void* __restrict__ ei_raw, const void* __restrict__ bat_raw) {
    int i = blockIdx.x * blockDim.x + threadIdx.x;
    const bool is64 = (g_is64 != 0);
    if (i < NE) {
        if (is64) {
            const long long* p = (const long long*)ei_raw;
            g_src[i] = (int)p[i];
            g_dst[i] = (int)p[NE + i];
        } else {
            const int* p = (const int*)ei_raw;
            g_src[i] = p[i];
            g_dst[i] = p[NE + i];
        }
    }
    if (i < NN) {
        g_bat[i] = is64 ? (int)((const long long*)bat_raw)[i]
                        : ((const int*)bat_raw)[i];
    }
}

__global__ void k_init() {
    int i = blockIdx.x * blockDim.x + threadIdx.x;
    if (i < NN) { g_cnt_i[i] = 0; g_cursor[i] = 0; }
    if (i < NG * C) g_pool[i] = 0.0f;
    if (i < NG) g_gcnt[i] = 0;
}

__global__ void k_hist() {
    int e = blockIdx.x * blockDim.x + threadIdx.x;
    if (e < NE) atomicAdd(&g_cnt_i[g_dst[e]], 1);
}

// dis = rsqrt(in_deg + 1)  and per-graph node counts
__global__ void k_dis() {
    int i = blockIdx.x * blockDim.x + threadIdx.x;
    if (i < NN) {
        g_dis[i] = rsqrtf((float)(g_cnt_i[i] + 1));
        atomicAdd(&g_gcnt[g_bat[i]], 1);
    }
}

// Single-block exclusive scan of g_cnt_i -> g_rs
__global__ void k_scan() {
    __shared__ int part[1024];
    const int t = threadIdx.x;
    const int CH = (NN + 1023) / 1024;   // 49
    int beg = t * CH;
    int end = beg + CH; if (end > NN) end = NN;
    int s = 0;
    for (int i = beg; i < end; i++) s += g_cnt_i[i];
    part[t] = s;
    __syncthreads();
    if (t == 0) {
        int run = 0;
        for (int i = 0; i < 1024; i++) { int v = part[i]; part[i] = run; run += v; }
    }
    __syncthreads();
    if (beg < NN) {
        int run = part[t];
        for (int i = beg; i < end; i++) { g_rs[i] = run; run += g_cnt_i[i]; }
    }
    if (t == 0) g_rs[NN] = NE;
}

__global__ void k_fill() {
    int e = blockIdx.x * blockDim.x + threadIdx.x;
    if (e < NE) {
        int d = g_dst[e];
        int off = atomicAdd(&g_cursor[d], 1);
        g_col[g_rs[d] + off] = g_src[e];
    }
}

// out = (X @ W) * dis[row].  BM=64 rows/block, 256 threads, 8x4 per-thread tile.
__global__ void k_gemm(const float* __restrict__ X, const float* __restrict__ W,
                       const float* __restrict__ dis, float* __restrict__ out) {
    extern __shared__ float sm[];
    float4* Ws4 = (float4*)sm;             // 128 x 32 float4 (64KB)
    float4* Xs4 = (float4*)(sm + C * C);   // 64 x 32 float4  (32KB)
    const int tid = threadIdx.x;
    const int bm = blockIdx.x * 64;

#pragma unroll
    for (int t = 0; t < 16; t++) {
        int idx = tid + t * 256;
        Ws4[idx] = ((const float4*)W)[idx];
    }
#pragma unroll
    for (int t = 0; t < 8; t++) {
        int idx = tid + t * 256;
        int row = idx >> 5, c4 = idx & 31;
        int gr = bm + row;
        float4 v = make_float4(0.f, 0.f, 0.f, 0.f);
        if (gr < NN) v = ((const float4*)X)[gr * 32 + c4];
        Xs4[idx] = v;
    }
    __syncthreads();

    const int tx = tid & 31;
    const int ty = tid >> 5;
    float acc[8][4];
#pragma unroll
    for (int i = 0; i < 8; i++)
#pragma unroll
        for (int j = 0; j < 4; j++) acc[i][j] = 0.f;

#pragma unroll 4
    for (int k4 = 0; k4 < 32; k4++) {
        float4 a4[8];
#pragma unroll
        for (int i = 0; i < 8; i++) a4[i] = Xs4[(ty * 8 + i) * 32 + k4];
#pragma unroll
        for (int kk = 0; kk < 4; kk++) {
            float4 b = Ws4[(k4 * 4 + kk) * 32 + tx];
#pragma unroll
            for (int i = 0; i < 8; i++) {
                float av = (kk == 0) ? a4[i].x : (kk == 1) ? a4[i].y : (kk == 2) ? a4[i].z : a4[i].w;
                acc[i][0] += av * b.x;
                acc[i][1] += av * b.y;
                acc[i][2] += av * b.z;
                acc[i][3] += av * b.w;
            }
        }
    }

#pragma unroll
    for (int i = 0; i < 8; i++) {
        int r = bm + ty * 8 + i;
        if (r < NN) {
            float s = dis[r];
            ((float4*)(out + r * C))[tx] =
                make_float4(acc[i][0] * s, acc[i][1] * s, acc[i][2] * s, acc[i][3] * s);
        }
    }
}

// Layer-1 aggregation: one warp per dst node. acc = hs[d] (self loop) + sum hs[col[e]].
// out = relu(dis[d]*acc + b1)
__global__ void k_agg_relu(const float* __restrict__ hs, const float* __restrict__ bias,
                           float* __restrict__ out) {
    int d = blockIdx.x * (blockDim.x >> 5) + (threadIdx.x >> 5);
    int lane = threadIdx.x & 31;
    if (d >= NN) return;
    const float4* hs4 = (const float4*)hs;
    float4 acc = hs4[d * 32 + lane];
    int beg = g_rs[d], end = g_rs[d + 1];
    for (int e = beg; e < end; e++) {
        int s = g_col[e];
        float4 v = hs4[s * 32 + lane];
        acc.x += v.x; acc.y += v.y; acc.z += v.z; acc.w += v.w;
    }
    float sc = g_dis[d];
    float4 bb = ((const float4*)bias)[lane];
    float4 o;
    o.x = fmaxf(fmaf(sc, acc.x, bb.x), 0.f);
    o.y = fmaxf(fmaf(sc, acc.y, bb.y), 0.f);
    o.z = fmaxf(fmaf(sc, acc.z, bb.z), 0.f);
    o.w = fmaxf(fmaf(sc, acc.w, bb.w), 0.f);
    ((float4*)out)[d * 32 + lane] = o;
}

// Layer-2 aggregation fused with mean-pool scatter (scalar atomics into [128 x 128]).
__global__ void k_agg_pool(const float* __restrict__ hs, const float* __restrict__ bias) {
    int d = blockIdx.x * (blockDim.x >> 5) + (threadIdx.x >> 5);
    int lane = threadIdx.x & 31;
    if (d >= NN) return;
    const float4* hs4 = (const float4*)hs;
    float4 acc = hs4[d * 32 + lane];
    int beg = g_rs[d], end = g_rs[d + 1];
    for (int e = beg; e < end; e++) {
        int s = g_col[e];
        float4 v = hs4[s * 32 + lane];
        acc.x += v.x; acc.y += v.y; acc.z += v.z; acc.w += v.w;
    }
    float sc = g_dis[d];
    float4 bb = ((const float4*)bias)[lane];
    float4 o;
    o.x = fmaxf(fmaf(sc, acc.x, bb.x), 0.f);
    o.y = fmaxf(fmaf(sc, acc.y, bb.y), 0.f);
    o.z = fmaxf(fmaf(sc, acc.z, bb.z), 0.f);
    o.w = fmaxf(fmaf(sc, acc.w, bb.w), 0.f);
    int g = g_bat[d];
    float* p = g_pool + g * C + lane * 4;
    atomicAdd(p + 0, o.x);
    atomicAdd(p + 1, o.y);
    atomicAdd(p + 2, o.z);
    atomicAdd(p + 3, o.w);
}

// Single block: 128 threads, one graph per thread. FC + log_softmax.
__global__ void k_fc(const float* __restrict__ Wfc, const float* __restrict__ bfc,
                     float* __restrict__ out) {
    __shared__ float Wf[C * OC];
    int t = threadIdx.x;
    for (int i = t; i < C * OC; i += 128) Wf[i] = Wfc[i];
    __syncthreads();

    float inv = 1.0f / fmaxf((float)g_gcnt[t], 1.0f);
    float acc[OC];
#pragma unroll
    for (int j = 0; j < OC; j++) acc[j] = bfc[j];
    for (int k = 0; k < C; k++) {
        float p = g_pool[t * C + k] * inv;
#pragma unroll
        for (int j = 0; j < OC; j++) acc[j] += p * Wf[k * OC + j];
    }
    float m = acc[0];
#pragma unroll
    for (int j = 1; j < OC; j++) m = fmaxf(m, acc[j]);
    float sum = 0.f;
#pragma unroll
    for (int j = 0; j < OC; j++) sum += expf(acc[j] - m);
    float lse = m + logf(sum);
#pragma unroll
    for (int j = 0; j < OC; j++) out[t * OC + j] = acc[j] - lse;
}

extern "C" void kernel_launch(void* const* d_in, const int* in_sizes, int n_in,
                              void* d_out, int out_size) {
    const float* x     = (const float*)d_in[0];
    const void*  ei    = d_in[1];
    const void*  batch = d_in[2];
    const float* W1    = (const float*)d_in[3];
    const float* b1    = (const float*)d_in[4];
    const float* W2    = (const float*)d_in[5];
    const float* b2    = (const float*)d_in[6];
    const float* Wfc   = (const float*)d_in[7];
    const float* bfc   = (const float*)d_in[8];
    float* out = (float*)d_out;

    float *A, *X2, *dis;
    cudaGetSymbolAddress((void**)&A,   g_A);
    cudaGetSymbolAddress((void**)&X2,  g_X2);
    cudaGetSymbolAddress((void**)&dis, g_dis);

    size_t smem = (size_t)(C * C + 64 * C) * sizeof(float);   // 96KB
    cudaFuncSetAttribute(k_gemm, cudaFuncAttributeMaxDynamicSharedMemorySize, (int)smem);

    // Normalize index dtypes (int64 vs int32) into int32 scratch
    k_detect<<<1, 32>>>((const int*)ei);
    k_convert<<<(NE + 255) / 256, 256>>>(ei, batch);

    // Graph structure (once per call, reused by both layers)
    k_init<<<(NN + 255) / 256, 256>>>();
    k_hist<<<(NE + 255) / 256, 256>>>();
    k_dis<<<(NN + 255) / 256, 256>>>();
    k_scan<<<1, 1024>>>();
    k_fill<<<(NE + 255) / 256, 256>>>();

    // Layer 1
    k_gemm<<<(NN + 63) / 64, 256, smem>>>(x, W1, dis, A);
    k_agg_relu<<<(NN + 7) / 8, 256>>>(A, b1, X2);

    // Layer 2
    k_gemm<<<(NN + 63) / 64, 256, smem>>>(X2, W2, dis, A);
    k_agg_pool<<<(NN + 7) / 8, 256>>>(A, b2);

    // Head
    k_fc<<<1, 128>>>(Wfc, bfc, out);
}

// round 5
// speedup vs baseline: 1.2143x; 1.2143x over previous
#include <cuda_runtime.h>

#define NN 50000
#define NE 800000
#define C  128
#define NG 128
#define OC 16

// Scratch (static device globals — no allocation in kernel_launch)
__device__ __align__(16) float g_A[NN * C];     // hs = (X@W)*dis  (layer output pre-agg)
__device__ __align__(16) float g_X2[NN * C];    // layer-2 input
__device__ __align__(16) float g_pool[NG * C];
__device__ float g_dis[NN];
__device__ int   g_src[NE];
__device__ int   g_dst[NE];
__device__ int   g_bat[NN];
__device__ int   g_cnt_i[NN];    // in-degree histogram (by dst)
__device__ int   g_cursor[NN];   // fill cursors (= row start copy)
__device__ int   g_rs[NN + 1];   // CSR row starts
__device__ int   g_col[NE];      // CSR column (src) ids
__device__ int   g_gcnt[NG];     // nodes per graph
__device__ int   g_is64;

// launch 0: detect int64 vs int32 edge buffer
__global__ void k_detect(const int* __restrict__ ei_raw) {
    if (threadIdx.x == 0 && blockIdx.x == 0) {
        int hi_or = 0, lo_ok = 1;
        for (int i = 0; i < 256; i++) {
            hi_or |= ei_raw[2 * i + 1];
            int lo = ei_raw[2 * i];
            lo_ok &= (lo >= 0 && lo < NN) ? 1 : 0;
        }
        g_is64 = (hi_or == 0 && lo_ok) ? 1 : 0;
    }
}

// launch 1: zero counters
__global__ void k_init() {
    int i = blockIdx.x * blockDim.x + threadIdx.x;
    if (i < NN) g_cnt_i[i] = 0;
    if (i < NG * C) g_pool[i] = 0.0f;
    if (i < NG) g_gcnt[i] = 0;
}

// launch 2: dtype-normalize + in-degree histogram + per-graph node counts
__global__ void k_convert_hist(const void* __restrict__ ei_raw, const void* __restrict__ bat_raw) {
    int i = blockIdx.x * blockDim.x + threadIdx.x;
    const bool is64 = (g_is64 != 0);
    if (i < NE) {
        int s, d;
        if (is64) {
            const long long* p = (const long long*)ei_raw;
            s = (int)p[i]; d = (int)p[NE + i];
        } else {
            const int* p = (const int*)ei_raw;
            s = p[i]; d = p[NE + i];
        }
        g_src[i] = s; g_dst[i] = d;
        atomicAdd(&g_cnt_i[d], 1);
    }
    if (i < NN) {
        int b = is64 ? (int)((const long long*)bat_raw)[i] : ((const int*)bat_raw)[i];
        g_bat[i] = b;
        atomicAdd(&g_gcnt[b], 1);
    }
}

// launch 3: exclusive scan -> row starts + cursors + dis = rsqrt(deg+1)
__global__ void k_scan_dis() {
    __shared__ int part[1024];
    const int t = threadIdx.x;
    const int CH = (NN + 1023) / 1024;   // 49
    int beg = t * CH;
    int end = beg + CH; if (end > NN) end = NN;
    int s = 0;
    for (int i = beg; i < end; i++) s += g_cnt_i[i];
    part[t] = s;
    __syncthreads();
    if (t == 0) {
        int run = 0;
        for (int i = 0; i < 1024; i++) { int v = part[i]; part[i] = run; run += v; }
    }
    __syncthreads();
    if (beg < NN) {
        int run = part[t];
        for (int i = beg; i < end; i++) {
            int c = g_cnt_i[i];
            g_rs[i] = run;
            g_cursor[i] = run;
            g_dis[i] = rsqrtf((float)(c + 1));
            run += c;
        }
    }
    if (t == 0) g_rs[NN] = NE;
}

// launch 4: CSR fill
__global__ void k_fill() {
    int e = blockIdx.x * blockDim.x + threadIdx.x;
    if (e < NE) {
        int d = g_dst[e];
        int off = atomicAdd(&g_cursor[d], 1);
        g_col[off] = g_src[e];
    }
}

// launches 5,7: out = (X @ W) * dis[row].  BM=64 rows/block, 256 threads.
// Inner loop uses packed fma.rn.f32x2 (2 FLOP-pairs per issue slot).
__global__ __launch_bounds__(256) void k_gemm(
        const float* __restrict__ X, const float* __restrict__ W,
        const float* __restrict__ dis, float* __restrict__ out) {
    extern __shared__ float sm[];
    float4* Ws4 = (float4*)sm;             // 128 x 32 float4 (64KB)
    float4* Xs4 = (float4*)(sm + C * C);   // 64 x 32 float4  (32KB)
    const unsigned long long* Ws8 = (const unsigned long long*)sm;  // b64 view of W tile
    const int tid = threadIdx.x;
    const int bm = blockIdx.x * 64;

#pragma unroll
    for (int t = 0; t < 16; t++) {
        int idx = tid + t * 256;
        Ws4[idx] = ((const float4*)W)[idx];
    }
#pragma unroll
    for (int t = 0; t < 8; t++) {
        int idx = tid + t * 256;
        int row = idx >> 5, c4 = idx & 31;
        int gr = bm + row;
        float4 v = make_float4(0.f, 0.f, 0.f, 0.f);
        if (gr < NN) v = ((const float4*)X)[gr * 32 + c4];
        Xs4[idx] = v;
    }
    __syncthreads();

    const int tx = tid & 31;
    const int ty = tid >> 5;

    // acc2[i][0] = cols (4tx, 4tx+1), acc2[i][1] = cols (4tx+2, 4tx+3), packed f32x2
    unsigned long long acc2[8][2];
#pragma unroll
    for (int i = 0; i < 8; i++) { acc2[i][0] = 0ULL; acc2[i][1] = 0ULL; }

#pragma unroll 2
    for (int k4 = 0; k4 < 32; k4++) {
        float4 a4[8];
#pragma unroll
        for (int i = 0; i < 8; i++) a4[i] = Xs4[(ty * 8 + i) * 32 + k4];  // warp-broadcast
#pragma unroll
        for (int kk = 0; kk < 4; kk++) {
            // b pair loads: cols (4tx,4tx+1) and (4tx+2,4tx+3) of W row k
            int base = ((k4 * 4 + kk) * 32 + tx) * 2;
            unsigned long long bxy = Ws8[base];
            unsigned long long bzw = Ws8[base + 1];
#pragma unroll
            for (int i = 0; i < 8; i++) {
                float av = (kk == 0) ? a4[i].x : (kk == 1) ? a4[i].y : (kk == 2) ? a4[i].z : a4[i].w;
                unsigned int ab = __float_as_uint(av);
                unsigned long long av2;
                asm("mov.b64 %0, {%1, %1};" : "=l"(av2) : "r"(ab));
                asm("fma.rn.f32x2 %0, %1, %2, %0;" : "+l"(acc2[i][0]) : "l"(av2), "l"(bxy));
                asm("fma.rn.f32x2 %0, %1, %2, %0;" : "+l"(acc2[i][1]) : "l"(av2), "l"(bzw));
            }
        }
    }

#pragma unroll
    for (int i = 0; i < 8; i++) {
        int r = bm + ty * 8 + i;
        if (r < NN) {
            float s = dis[r];
            unsigned int x0, x1, x2, x3;
            asm("mov.b64 {%0, %1}, %2;" : "=r"(x0), "=r"(x1) : "l"(acc2[i][0]));
            asm("mov.b64 {%0, %1}, %2;" : "=r"(x2), "=r"(x3) : "l"(acc2[i][1]));
            ((float4*)(out + r * C))[tx] = make_float4(
                __uint_as_float(x0) * s, __uint_as_float(x1) * s,
                __uint_as_float(x2) * s, __uint_as_float(x3) * s);
        }
    }
}

// gather core: acc = hs[d] (self loop) + sum_{e in row d} hs[col[e]], 4-way unrolled
__device__ __forceinline__ float4 agg_row(const float4* __restrict__ hs4, int d, int lane) {
    float4 acc = hs4[d * 32 + lane];
    int e = g_rs[d], end = g_rs[d + 1];
    for (; e + 4 <= end; e += 4) {
        int s0 = g_col[e], s1 = g_col[e + 1], s2 = g_col[e + 2], s3 = g_col[e + 3];
        float4 v0 = hs4[s0 * 32 + lane];
        float4 v1 = hs4[s1 * 32 + lane];
        float4 v2 = hs4[s2 * 32 + lane];
        float4 v3 = hs4[s3 * 32 + lane];
        acc.x += v0.x + v1.x + v2.x + v3.x;
        acc.y += v0.y + v1.y + v2.y + v3.y;
        acc.z += v0.z + v1.z + v2.z + v3.z;
        acc.w += v0.w + v1.w + v2.w + v3.w;
    }
    for (; e < end; e++) {
        int s = g_col[e];
        float4 v = hs4[s * 32 + lane];
        acc.x += v.x; acc.y += v.y; acc.z += v.z; acc.w += v.w;
    }
    return acc;
}

// launch 6: layer-1 aggregation + relu.  One warp per dst node.
__global__ void k_agg_relu(const float* __restrict__ hs, const float* __restrict__ bias,
                           float* __restrict__ out) {
    int d = blockIdx.x * (blockDim.x >> 5) + (threadIdx.x >> 5);
    int lane = threadIdx.x & 31;
    if (d >= NN) return;
    float4 acc = agg_row((const float4*)hs, d, lane);
    float sc = g_dis[d];
    float4 bb = ((const float4*)bias)[lane];
    float4 o;
    o.x = fmaxf(fmaf(sc, acc.x, bb.x), 0.f);
    o.y = fmaxf(fmaf(sc, acc.y, bb.y), 0.f);
    o.z = fmaxf(fmaf(sc, acc.z, bb.z), 0.f);
    o.w = fmaxf(fmaf(sc, acc.w, bb.w), 0.f);
    ((float4*)out)[d * 32 + lane] = o;
}

// launch 8: layer-2 aggregation + relu + mean-pool scatter
__global__ void k_agg_pool(const float* __restrict__ hs, const float* __restrict__ bias) {
    int d = blockIdx.x * (blockDim.x >> 5) + (threadIdx.x >> 5);
    int lane = threadIdx.x & 31;
    if (d >= NN) return;
    float4 acc = agg_row((const float4*)hs, d, lane);
    float sc = g_dis[d];
    float4 bb = ((const float4*)bias)[lane];
    float4 o;
    o.x = fmaxf(fmaf(sc, acc.x, bb.x), 0.f);
    o.y = fmaxf(fmaf(sc, acc.y, bb.y), 0.f);
    o.z = fmaxf(fmaf(sc, acc.z, bb.z), 0.f);
    o.w = fmaxf(fmaf(sc, acc.w, bb.w), 0.f);
    int g = g_bat[d];
    float* p = g_pool + g * C + lane * 4;
    atomicAdd(p + 0, o.x);
    atomicAdd(p + 1, o.y);
    atomicAdd(p + 2, o.z);
    atomicAdd(p + 3, o.w);
}

// launch 9: 128 threads, one graph per thread. FC + log_softmax.
__global__ void k_fc(const float* __restrict__ Wfc, const float* __restrict__ bfc,
                     float* __restrict__ out) {
    __shared__ float Wf[C * OC];
    int t = threadIdx.x;
    for (int i = t; i < C * OC; i += 128) Wf[i] = Wfc[i];
    __syncthreads();

    float inv = 1.0f / fmaxf((float)g_gcnt[t], 1.0f);
    float acc[OC];
#pragma unroll
    for (int j = 0; j < OC; j++) acc[j] = bfc[j];
    for (int k = 0; k < C; k++) {
        float p = g_pool[t * C + k] * inv;
#pragma unroll
        for (int j = 0; j < OC; j++) acc[j] += p * Wf[k * OC + j];
    }
    float m = acc[0];
#pragma unroll
    for (int j = 1; j < OC; j++) m = fmaxf(m, acc[j]);
    float sum = 0.f;
#pragma unroll
    for (int j = 0; j < OC; j++) sum += expf(acc[j] - m);
    float lse = m + logf(sum);
#pragma unroll
    for (int j = 0; j < OC; j++) out[t * OC + j] = acc[j] - lse;
}

extern "C" void kernel_launch(void* const* d_in, const int* in_sizes, int n_in,
                              void* d_out, int out_size) {
    const float* x     = (const float*)d_in[0];
    const void*  ei    = d_in[1];
    const void*  batch = d_in[2];
    const float* W1    = (const float*)d_in[3];
    const float* b1    = (const float*)d_in[4];
    const float* W2    = (const float*)d_in[5];
    const float* b2    = (const float*)d_in[6];
    const float* Wfc   = (const float*)d_in[7];
    const float* bfc   = (const float*)d_in[8];
    float* out = (float*)d_out;

    float *A, *X2, *dis;
    cudaGetSymbolAddress((void**)&A,   g_A);
    cudaGetSymbolAddress((void**)&X2,  g_X2);
    cudaGetSymbolAddress((void**)&dis, g_dis);

    size_t smem = (size_t)(C * C + 64 * C) * sizeof(float);   // 96KB
    cudaFuncSetAttribute(k_gemm, cudaFuncAttributeMaxDynamicSharedMemorySize, (int)smem);

    k_detect<<<1, 32>>>((const int*)ei);                      // 0
    k_init<<<(NG * C + 255) / 256 > (NN + 255) / 256 ? (NG * C + 255) / 256 : (NN + 255) / 256, 256>>>(); // 1
    k_convert_hist<<<(NE + 255) / 256, 256>>>(ei, batch);     // 2
    k_scan_dis<<<1, 1024>>>();                                // 3
    k_fill<<<(NE + 255) / 256, 256>>>();                      // 4

    // Layer 1
    k_gemm<<<(NN + 63) / 64, 256, smem>>>(x, W1, dis, A);     // 5  <- ncu -s 5 -c 1 lands here
    k_agg_relu<<<(NN + 7) / 8, 256>>>(A, b1, X2);             // 6

    // Layer 2
    k_gemm<<<(NN + 63) / 64, 256, smem>>>(X2, W2, dis, A);    // 7
    k_agg_pool<<<(NN + 7) / 8, 256>>>(A, b2);                 // 8

    // Head
    k_fc<<<1, 128>>>(Wfc, bfc, out);                          // 9
}

// round 7
// speedup vs baseline: 1.7382x; 1.4314x over previous
#include <cuda_runtime.h>

#define NN 50000
#define NE 800000
#define C  128
#define NG 128
#define OC 16
#define NBLK 196   // ceil(50000/256)

// Scratch (static device globals — no allocation in kernel_launch)
__device__ __align__(16) float g_A[NN * C];     // hs = (X@W)*dis  (layer output pre-agg)
__device__ __align__(16) float g_X2[NN * C];    // layer-2 input
__device__ __align__(16) float g_pool[NG * C];
__device__ float g_dis[NN];
__device__ int   g_src[NE];
__device__ int   g_dst[NE];
__device__ int   g_bat[NN];
__device__ int   g_cnt_i[NN];    // in-degree histogram (by dst)
__device__ int   g_cursor[NN];   // fill cursors
__device__ int   g_rs[NN + 1];   // CSR row starts
__device__ int   g_col[NE];      // CSR column (src) ids
__device__ int   g_gcnt[NG];     // nodes per graph
__device__ int   g_bsum[NBLK];   // per-block degree sums
__device__ int   g_boff[NBLK];   // per-block scan offsets
__device__ int   g_is64;

// launch 0: zero counters + dtype detect (block 0 thread 0)
__global__ void k_init(const int* __restrict__ ei_raw) {
    int i = blockIdx.x * blockDim.x + threadIdx.x;
    if (i == 0) {
        int hi_or = 0, lo_ok = 1;
        for (int j = 0; j < 256; j++) {
            hi_or |= ei_raw[2 * j + 1];
            int lo = ei_raw[2 * j];
            lo_ok &= (lo >= 0 && lo < NN) ? 1 : 0;
        }
        g_is64 = (hi_or == 0 && lo_ok) ? 1 : 0;
    }
    if (i < NN) g_cnt_i[i] = 0;
    if (i < NG * C) g_pool[i] = 0.0f;
    if (i < NG) g_gcnt[i] = 0;
}

// launch 1: dtype-normalize + in-degree histogram + per-graph node counts
__global__ void k_convert_hist(const void* __restrict__ ei_raw, const void* __restrict__ bat_raw) {
    int i = blockIdx.x * blockDim.x + threadIdx.x;
    const bool is64 = (g_is64 != 0);
    if (i < NE) {
        int s, d;
        if (is64) {
            const long long* p = (const long long*)ei_raw;
            s = (int)p[i]; d = (int)p[NE + i];
        } else {
            const int* p = (const int*)ei_raw;
            s = p[i]; d = p[NE + i];
        }
        g_src[i] = s; g_dst[i] = d;
        atomicAdd(&g_cnt_i[d], 1);
    }
    if (i < NN) {
        int b = is64 ? (int)((const long long*)bat_raw)[i] : ((const int*)bat_raw)[i];
        g_bat[i] = b;
        atomicAdd(&g_gcnt[b], 1);
    }
}

// launch 2: per-block degree sums (196 blocks x 256)
__global__ void k_scan1() {
    int i = blockIdx.x * blockDim.x + threadIdx.x;
    int c = (i < NN) ? g_cnt_i[i] : 0;
#pragma unroll
    for (int off = 16; off > 0; off >>= 1)
        c += __shfl_down_sync(0xffffffffu, c, off);
    __shared__ int ws[8];
    int lane = threadIdx.x & 31, w = threadIdx.x >> 5;
    if (lane == 0) ws[w] = c;
    __syncthreads();
    if (threadIdx.x == 0) {
        int s = 0;
#pragma unroll
        for (int j = 0; j < 8; j++) s += ws[j];
        g_bsum[blockIdx.x] = s;
    }
}

// launch 3: exclusive scan of 196 block sums (one block, Hillis-Steele over 256)
__global__ void k_scan2() {
    __shared__ int s[256];
    int t = threadIdx.x;
    int v = (t < NBLK) ? g_bsum[t] : 0;
    s[t] = v;
    __syncthreads();
#pragma unroll
    for (int off = 1; off < 256; off <<= 1) {
        int x = (t >= off) ? s[t - off] : 0;
        __syncthreads();
        s[t] += x;
        __syncthreads();
    }
    if (t < NBLK) g_boff[t] = s[t] - v;   // exclusive
}

// launch 4: block-level exclusive scan + write rs/cursor/dis
__global__ void k_scan3() {
    int t = threadIdx.x;
    int i = blockIdx.x * blockDim.x + t;
    int c = (i < NN) ? g_cnt_i[i] : 0;
    int lane = t & 31, w = t >> 5;
    // warp inclusive scan
    int incl = c;
#pragma unroll
    for (int off = 1; off < 32; off <<= 1) {
        int n = __shfl_up_sync(0xffffffffu, incl, off);
        if (lane >= off) incl += n;
    }
    __shared__ int wsum[8], woff[8];
    if (lane == 31) wsum[w] = incl;
    __syncthreads();
    if (t == 0) {
        int run = 0;
#pragma unroll
        for (int j = 0; j < 8; j++) { woff[j] = run; run += wsum[j]; }
    }
    __syncthreads();
    if (i < NN) {
        int pre = (incl - c) + woff[w] + g_boff[blockIdx.x];
        g_rs[i] = pre;
        g_cursor[i] = pre;
        g_dis[i] = rsqrtf((float)(c + 1));
    }
    if (i == 0) g_rs[NN] = NE;
}

// launches 5,8: out = (X @ W) * dis[row].  BM=64 rows/block, 256 threads.
// Inner loop uses packed fma.rn.f32x2.
__global__ __launch_bounds__(256) void k_gemm(
        const float* __restrict__ X, const float* __restrict__ W,
        const float* __restrict__ dis, float* __restrict__ out) {
    extern __shared__ float sm[];
    float4* Ws4 = (float4*)sm;             // 128 x 32 float4 (64KB)
    float4* Xs4 = (float4*)(sm + C * C);   // 64 x 32 float4  (32KB)
    const unsigned long long* Ws8 = (const unsigned long long*)sm;
    const int tid = threadIdx.x;
    const int bm = blockIdx.x * 64;

#pragma unroll
    for (int t = 0; t < 16; t++) {
        int idx = tid + t * 256;
        Ws4[idx] = ((const float4*)W)[idx];
    }
#pragma unroll
    for (int t = 0; t < 8; t++) {
        int idx = tid + t * 256;
        int row = idx >> 5, c4 = idx & 31;
        int gr = bm + row;
        float4 v = make_float4(0.f, 0.f, 0.f, 0.f);
        if (gr < NN) v = ((const float4*)X)[gr * 32 + c4];
        Xs4[idx] = v;
    }
    __syncthreads();

    const int tx = tid & 31;
    const int ty = tid >> 5;

    unsigned long long acc2[8][2];
#pragma unroll
    for (int i = 0; i < 8; i++) { acc2[i][0] = 0ULL; acc2[i][1] = 0ULL; }

#pragma unroll 2
    for (int k4 = 0; k4 < 32; k4++) {
        float4 a4[8];
#pragma unroll
        for (int i = 0; i < 8; i++) a4[i] = Xs4[(ty * 8 + i) * 32 + k4];  // warp-broadcast
#pragma unroll
        for (int kk = 0; kk < 4; kk++) {
            int base = ((k4 * 4 + kk) * 32 + tx) * 2;
            unsigned long long bxy = Ws8[base];
            unsigned long long bzw = Ws8[base + 1];
#pragma unroll
            for (int i = 0; i < 8; i++) {
                float av = (kk == 0) ? a4[i].x : (kk == 1) ? a4[i].y : (kk == 2) ? a4[i].z : a4[i].w;
                unsigned int ab = __float_as_uint(av);
                unsigned long long av2;
                asm("mov.b64 %0, {%1, %1};" : "=l"(av2) : "r"(ab));
                asm("fma.rn.f32x2 %0, %1, %2, %0;" : "+l"(acc2[i][0]) : "l"(av2), "l"(bxy));
                asm("fma.rn.f32x2 %0, %1, %2, %0;" : "+l"(acc2[i][1]) : "l"(av2), "l"(bzw));
            }
        }
    }

#pragma unroll
    for (int i = 0; i < 8; i++) {
        int r = bm + ty * 8 + i;
        if (r < NN) {
            float s = dis[r];
            unsigned int x0, x1, x2, x3;
            asm("mov.b64 {%0, %1}, %2;" : "=r"(x0), "=r"(x1) : "l"(acc2[i][0]));
            asm("mov.b64 {%0, %1}, %2;" : "=r"(x2), "=r"(x3) : "l"(acc2[i][1]));
            ((float4*)(out + r * C))[tx] = make_float4(
                __uint_as_float(x0) * s, __uint_as_float(x1) * s,
                __uint_as_float(x2) * s, __uint_as_float(x3) * s);
        }
    }
}

// launch 6: CSR fill (independent of gemm; placed after so gemm is launch 5)
__global__ void k_fill() {
    int e = blockIdx.x * blockDim.x + threadIdx.x;
    if (e < NE) {
        int d = g_dst[e];
        int off = atomicAdd(&g_cursor[d], 1);
        g_col[off] = g_src[e];
    }
}

// gather core: acc = hs[d] (self loop) + sum_{e in row d} hs[col[e]], 4-way unrolled
__device__ __forceinline__ float4 agg_row(const float4* __restrict__ hs4, int d, int lane) {
    float4 acc = hs4[d * 32 + lane];
    int e = g_rs[d], end = g_rs[d + 1];
    for (; e + 4 <= end; e += 4) {
        int s0 = g_col[e], s1 = g_col[e + 1], s2 = g_col[e + 2], s3 = g_col[e + 3];
        float4 v0 = hs4[s0 * 32 + lane];
        float4 v1 = hs4[s1 * 32 + lane];
        float4 v2 = hs4[s2 * 32 + lane];
        float4 v3 = hs4[s3 * 32 + lane];
        acc.x += v0.x + v1.x + v2.x + v3.x;
        acc.y += v0.y + v1.y + v2.y + v3.y;
        acc.z += v0.z + v1.z + v2.z + v3.z;
        acc.w += v0.w + v1.w + v2.w + v3.w;
    }
    for (; e < end; e++) {
        int s = g_col[e];
        float4 v = hs4[s * 32 + lane];
        acc.x += v.x; acc.y += v.y; acc.z += v.z; acc.w += v.w;
    }
    return acc;
}

// launch 7: layer-1 aggregation + relu.  One warp per dst node.
__global__ void k_agg_relu(const float* __restrict__ hs, const float* __restrict__ bias,
                           float* __restrict__ out) {
    int d = blockIdx.x * (blockDim.x >> 5) + (threadIdx.x >> 5);
    int lane = threadIdx.x & 31;
    if (d >= NN) return;
    float4 acc = agg_row((const float4*)hs, d, lane);
    float sc = g_dis[d];
    float4 bb = ((const float4*)bias)[lane];
    float4 o;
    o.x = fmaxf(fmaf(sc, acc.x, bb.x), 0.f);
    o.y = fmaxf(fmaf(sc, acc.y, bb.y), 0.f);
    o.z = fmaxf(fmaf(sc, acc.z, bb.z), 0.f);
    o.w = fmaxf(fmaf(sc, acc.w, bb.w), 0.f);
    ((float4*)out)[d * 32 + lane] = o;
}

// launch 9: layer-2 aggregation + relu + mean-pool scatter
__global__ void k_agg_pool(const float* __restrict__ hs, const float* __restrict__ bias) {
    int d = blockIdx.x * (blockDim.x >> 5) + (threadIdx.x >> 5);
    int lane = threadIdx.x & 31;
    if (d >= NN) return;
    float4 acc = agg_row((const float4*)hs, d, lane);
    float sc = g_dis[d];
    float4 bb = ((const float4*)bias)[lane];
    float4 o;
    o.x = fmaxf(fmaf(sc, acc.x, bb.x), 0.f);
    o.y = fmaxf(fmaf(sc, acc.y, bb.y), 0.f);
    o.z = fmaxf(fmaf(sc, acc.z, bb.z), 0.f);
    o.w = fmaxf(fmaf(sc, acc.w, bb.w), 0.f);
    int g = g_bat[d];
    float* p = g_pool + g * C + lane * 4;
    atomicAdd(p + 0, o.x);
    atomicAdd(p + 1, o.y);
    atomicAdd(p + 2, o.z);
    atomicAdd(p + 3, o.w);
}

// launch 10: 128 threads, one graph per thread. FC + log_softmax.
__global__ void k_fc(const float* __restrict__ Wfc, const float* __restrict__ bfc,
                     float* __restrict__ out) {
    __shared__ float Wf[C * OC];
    int t = threadIdx.x;
    for (int i = t; i < C * OC; i += 128) Wf[i] = Wfc[i];
    __syncthreads();

    float inv = 1.0f / fmaxf((float)g_gcnt[t], 1.0f);
    float acc[OC];
#pragma unroll
    for (int j = 0; j < OC; j++) acc[j] = bfc[j];
    for (int k = 0; k < C; k++) {
        float p = g_pool[t * C + k] * inv;
#pragma unroll
        for (int j = 0; j < OC; j++) acc[j] += p * Wf[k * OC + j];
    }
    float m = acc[0];
#pragma unroll
    for (int j = 1; j < OC; j++) m = fmaxf(m, acc[j]);
    float sum = 0.f;
#pragma unroll
    for (int j = 0; j < OC; j++) sum += expf(acc[j] - m);
    float lse = m + logf(sum);
#pragma unroll
    for (int j = 0; j < OC; j++) out[t * OC + j] = acc[j] - lse;
}

extern "C" void kernel_launch(void* const* d_in, const int* in_sizes, int n_in,
                              void* d_out, int out_size) {
    const float* x     = (const float*)d_in[0];
    const void*  ei    = d_in[1];
    const void*  batch = d_in[2];
    const float* W1    = (const float*)d_in[3];
    const float* b1    = (const float*)d_in[4];
    const float* W2    = (const float*)d_in[5];
    const float* b2    = (const float*)d_in[6];
    const float* Wfc   = (const float*)d_in[7];
    const float* bfc   = (const float*)d_in[8];
    float* out = (float*)d_out;

    float *A, *X2, *dis;
    cudaGetSymbolAddress((void**)&A,   g_A);
    cudaGetSymbolAddress((void**)&X2,  g_X2);
    cudaGetSymbolAddress((void**)&dis, g_dis);

    size_t smem = (size_t)(C * C + 64 * C) * sizeof(float);   // 96KB
    cudaFuncSetAttribute(k_gemm, cudaFuncAttributeMaxDynamicSharedMemorySize, (int)smem);

    int initg = (NG * C + 255) / 256;            // 64 blocks covers NG*C; NN needs 196
    if (initg < NBLK) initg = NBLK;

    k_init<<<initg, 256>>>((const int*)ei);               // 0
    k_convert_hist<<<(NE + 255) / 256, 256>>>(ei, batch); // 1
    k_scan1<<<NBLK, 256>>>();                             // 2
    k_scan2<<<1, 256>>>();                                // 3
    k_scan3<<<NBLK, 256>>>();                             // 4

    // Layer 1 (gemm independent of CSR fill)
    k_gemm<<<(NN + 63) / 64, 256, smem>>>(x, W1, dis, A); // 5  <- ncu -s 5 -c 1
    k_fill<<<(NE + 255) / 256, 256>>>();                  // 6
    k_agg_relu<<<(NN + 7) / 8, 256>>>(A, b1, X2);         // 7

    // Layer 2
    k_gemm<<<(NN + 63) / 64, 256, smem>>>(X2, W2, dis, A);// 8
    k_agg_pool<<<(NN + 7) / 8, 256>>>(A, b2);             // 9

    // Head
    k_fc<<<1, 128>>>(Wfc, bfc, out);                      // 10
}